// round 1
// baseline (speedup 1.0000x reference)
#include <cuda_runtime.h>
#include <math.h>

#define NBITS 20
#define NSUB  ((1u << NBITS) - 1u)   // 1048575 subsets

// Scratch: 20 bit-masked sums of w + total sum of w.
__device__ float g_sums[NBITS + 1];

__global__ void mil_init_kernel() {
    int t = threadIdx.x;
    if (t < NBITS + 1) g_sums[t] = 0.0f;
}

// Streaming reduction over w: acc[b] = sum of w[e] where bit b of (e+1) is set,
// acc[NBITS] = sum of all w.
__global__ void __launch_bounds__(256) mil_reduce_kernel(const float* __restrict__ w) {
    const int tid      = blockIdx.x * blockDim.x + threadIdx.x;
    const int nthreads = gridDim.x * blockDim.x;

    float acc[NBITS + 1];
#pragma unroll
    for (int b = 0; b <= NBITS; b++) acc[b] = 0.0f;

    const int N4 = (int)(NSUB >> 2);           // 262143 full float4 groups
    const float4* __restrict__ w4 = (const float4*)w;

    for (int g = tid; g < N4; g += nthreads) {
        float4 v = w4[g];
        unsigned i0 = 4u * (unsigned)g + 1u;   // subset index of v.x
        float vv[4] = {v.x, v.y, v.z, v.w};
#pragma unroll
        for (int k = 0; k < 4; k++) {
            unsigned i  = i0 + (unsigned)k;
            unsigned vb = __float_as_uint(vv[k]);
            acc[NBITS] += vv[k];
#pragma unroll
            for (int b = 0; b < NBITS; b++) {
                // mask = 0xFFFFFFFF if bit b of i set, else 0 (2 SHF + LOP + FADD)
                unsigned m = (unsigned)(((int)(i << (31 - b))) >> 31);
                acc[b] += __uint_as_float(vb & m);
            }
        }
    }

    // Tail: elements e = 4*N4 .. NSUB-1 (3 elements)
    {
        unsigned tail = NSUB - (unsigned)N4 * 4u;  // 3
        if ((unsigned)tid < tail) {
            unsigned e = (unsigned)N4 * 4u + (unsigned)tid;
            float v = w[e];
            unsigned i  = e + 1u;
            unsigned vb = __float_as_uint(v);
            acc[NBITS] += v;
#pragma unroll
            for (int b = 0; b < NBITS; b++) {
                unsigned m = (unsigned)(((int)(i << (31 - b))) >> 31);
                acc[b] += __uint_as_float(vb & m);
            }
        }
    }

    // Warp reduce each of 21 accumulators
#pragma unroll
    for (int b = 0; b <= NBITS; b++) {
        float s = acc[b];
#pragma unroll
        for (int o = 16; o > 0; o >>= 1)
            s += __shfl_xor_sync(0xFFFFFFFFu, s, o);
        acc[b] = s;
    }

    __shared__ float smem[8][NBITS + 1];
    int warp = threadIdx.x >> 5;
    int lane = threadIdx.x & 31;
    if (lane == 0) {
#pragma unroll
        for (int b = 0; b <= NBITS; b++) smem[warp][b] = acc[b];
    }
    __syncthreads();

    if (warp == 0 && lane <= NBITS) {
        float s = 0.0f;
        int nw = blockDim.x >> 5;
        for (int ww = 0; ww < nw; ww++) s += smem[ww][lane];
        atomicAdd(&g_sums[lane], s);
    }
}

// Epilogue: combine 21 sums with log-prob terms. Single thread, O(20).
__global__ void mil_finalize_kernel(const float* __restrict__ yprob,
                                    const int*   __restrict__ Yp,
                                    int has_Y,
                                    float* __restrict__ out) {
    if (threadIdx.x == 0 && blockIdx.x == 0) {
        // Y encoding-robust check: Python int 1 -> bits != 0, 0 -> bits == 0.
        int y_nonzero = 1;
        if (has_Y) y_nonzero = (Yp[0] != 0);

        double logp[NBITS], log1mp[NBITS];
        double base = 0.0;
#pragma unroll
        for (int j = 0; j < NBITS; j++) {
            double p = (double)yprob[j];
            logp[j]   = log(p);
            log1mp[j] = log(1.0 - p);
            base += log1mp[j];
        }

        if (y_nonzero) {
            double W   = (double)g_sums[NBITS];
            double res = base * W;
#pragma unroll
            for (int b = 0; b < NBITS; b++) {
                int j = NBITS - 1 - b;   // column j <-> bit (NBITS-1-j)
                res += (logp[j] - log1mp[j]) * (double)g_sums[b];
            }
            out[0] = (float)res;
        } else {
            out[0] = (float)((double)NSUB * base);
        }
    }
}

extern "C" void kernel_launch(void* const* d_in, const int* in_sizes, int n_in,
                              void* d_out, int out_size) {
    const float* yprob = (const float*)d_in[0];
    const float* w     = (const float*)d_in[1];
    const int*   Yp    = (n_in >= 3) ? (const int*)d_in[2] : nullptr;
    float*       out   = (float*)d_out;
    (void)in_sizes; (void)out_size;

    mil_init_kernel<<<1, 32>>>();
    mil_reduce_kernel<<<512, 256>>>(w);
    mil_finalize_kernel<<<1, 32>>>(yprob, Yp, Yp != nullptr ? 1 : 0, out);
}

// round 2
// speedup vs baseline: 1.0048x; 1.0048x over previous
#include <cuda_runtime.h>
#include <math.h>

#define NBITS   20
#define NSUB    ((1u << NBITS) - 1u)    // 1048575 elements in w
#define NCHUNK  (1 << (NBITS - 5))      // 32768 chunks of 32
#define NBLOCKS 128
#define NTPB    256

// Per-block partial sums: [block][21 bins]. Fully overwritten every launch -> no init needed.
__device__ float g_part[NBLOCKS][NBITS + 1];

__global__ void __launch_bounds__(NTPB) mil_reduce_kernel(const float* __restrict__ w) {
    const int c    = blockIdx.x * NTPB + threadIdx.x;   // chunk id, 0..32767 (exact cover)
    const int base = c << 5;                            // first element index e of the chunk

    // ---- load 32 elements v[0..31] (e = base+k) ----
    float v[32];
    const float4* __restrict__ w4 = (const float4*)w;
    if (c != NCHUNK - 1) {
#pragma unroll
        for (int g = 0; g < 8; g++) {
            float4 t = w4[(base >> 2) + g];
            v[4*g+0] = t.x; v[4*g+1] = t.y; v[4*g+2] = t.z; v[4*g+3] = t.w;
        }
    } else {
        // last chunk: e = 1048544..1048574 exist; e = 1048575 does not (w has 2^20-1 elems)
#pragma unroll
        for (int g = 0; g < 7; g++) {
            float4 t = w4[(base >> 2) + g];
            v[4*g+0] = t.x; v[4*g+1] = t.y; v[4*g+2] = t.z; v[4*g+3] = t.w;
        }
        v[28] = w[base + 28];
        v[29] = w[base + 29];
        v[30] = w[base + 30];
        v[31] = 0.0f;
    }

    // u[j] = w value whose subset index i has low-5-bits == j (i = base+1+k -> j = k+1)
    // u[0] = 0 (the boundary element v[31] has i = base+32, handled separately)
    float u[32];
    u[0] = 0.0f;
#pragma unroll
    for (int j = 1; j < 32; j++) u[j] = v[j - 1];
    const float v31 = v[31];

    // ---- binary partial-sum tree over u ----
    float T1[16], T2[8], T3[4], T4[2];
#pragma unroll
    for (int k = 0; k < 16; k++) T1[k] = u[2*k] + u[2*k+1];
#pragma unroll
    for (int k = 0; k < 8;  k++) T2[k] = T1[2*k] + T1[2*k+1];
#pragma unroll
    for (int k = 0; k < 4;  k++) T3[k] = T2[2*k] + T2[2*k+1];
#pragma unroll
    for (int k = 0; k < 2;  k++) T4[k] = T3[2*k] + T3[2*k+1];
    const float S = T4[0] + T4[1];      // sum of first 31 elements (i in [base+1, base+31])

    // low-bit sums: B_b = sum over j with bit b of j set
    float B0 = 0.0f, B1 = 0.0f, B2 = 0.0f, B3 = 0.0f;
#pragma unroll
    for (int j = 1; j < 32; j += 2) B0 += u[j];
#pragma unroll
    for (int k = 1; k < 16; k += 2) B1 += T1[k];
#pragma unroll
    for (int k = 1; k < 8;  k += 2) B2 += T2[k];
    B3 = T3[1] + T3[3];
    const float B4 = T4[1];

    // ---- per-chunk contribution vector p[0..20] ----
    float p[NBITS + 1];
    p[0] = B0; p[1] = B1; p[2] = B2; p[3] = B3; p[4] = B4;
    p[NBITS] = S + v31;                 // total-sum bin

    // high bits: bit b (b>=5) of i equals bit (b-5) of c for the 31 in-chunk elements,
    // and bit (b-5) of (c+1) for the boundary element v31 (i = base+32, low bits 0).
    const unsigned cc = (unsigned)c;
    const unsigned c1 = (unsigned)c + 1u;   // c=32767 -> v31=0, so overflow pattern harmless
    const unsigned sb = __float_as_uint(S);
    const unsigned vb = __float_as_uint(v31);
#pragma unroll
    for (int b = 5; b < NBITS; b++) {
        const int sh = 31 - (b - 5);
        unsigned m1 = (unsigned)(((int)(cc << sh)) >> 31);
        unsigned m2 = (unsigned)(((int)(c1 << sh)) >> 31);
        p[b] = __uint_as_float(sb & m1) + __uint_as_float(vb & m2);
    }

    // ---- block reduction of the 21-vector ----
    __shared__ float red[NTPB][NBITS + 2];   // +1 pad to avoid systematic conflicts
    const int tid = threadIdx.x;
#pragma unroll
    for (int b = 0; b <= NBITS; b++) red[tid][b] = p[b];
    __syncthreads();

#pragma unroll
    for (int s = NTPB / 2; s >= 1; s >>= 1) {
        if (tid < s) {
#pragma unroll
            for (int b = 0; b <= NBITS; b++) red[tid][b] += red[tid + s][b];
        }
        __syncthreads();
    }

    if (tid <= NBITS) g_part[blockIdx.x][tid] = red[0][tid];
}

// Combine per-block partials with the O(20) log-prob epilogue.
__global__ void mil_finalize_kernel(const float* __restrict__ yprob,
                                    const int*   __restrict__ Yp,
                                    int has_Y,
                                    float* __restrict__ out) {
    __shared__ float s[NBITS + 1];
    const int t = threadIdx.x;
    if (t <= NBITS) {
        float a = 0.0f;
        for (int i = 0; i < NBLOCKS; i++) a += g_part[i][t];
        s[t] = a;
    }
    __syncthreads();

    if (t == 0) {
        int y_nonzero = 1;
        if (has_Y) y_nonzero = (Yp[0] != 0);

        double logp[NBITS], log1mp[NBITS];
        double basee = 0.0;
#pragma unroll
        for (int j = 0; j < NBITS; j++) {
            double pp = (double)yprob[j];
            logp[j]   = log(pp);
            log1mp[j] = log(1.0 - pp);
            basee += log1mp[j];
        }

        if (y_nonzero) {
            double W   = (double)s[NBITS];
            double res = basee * W;
#pragma unroll
            for (int b = 0; b < NBITS; b++) {
                int j = NBITS - 1 - b;      // column j <-> bit (NBITS-1-j) of subset index
                res += (logp[j] - log1mp[j]) * (double)s[b];
            }
            out[0] = (float)res;
        } else {
            out[0] = (float)((double)NSUB * basee);
        }
    }
}

extern "C" void kernel_launch(void* const* d_in, const int* in_sizes, int n_in,
                              void* d_out, int out_size) {
    const float* yprob = (const float*)d_in[0];
    const float* w     = (const float*)d_in[1];
    const int*   Yp    = (n_in >= 3) ? (const int*)d_in[2] : nullptr;
    float*       out   = (float*)d_out;
    (void)in_sizes; (void)out_size;

    mil_reduce_kernel<<<NBLOCKS, NTPB>>>(w);
    mil_finalize_kernel<<<1, 32>>>(yprob, Yp, Yp != nullptr ? 1 : 0, out);
}

// round 3
// speedup vs baseline: 3.6358x; 3.6185x over previous
#include <cuda_runtime.h>
#include <math.h>

#define NBITS   20
#define NSUB    ((1u << NBITS) - 1u)    // 1048575 elements in w
#define NCHUNK  (1 << (NBITS - 5))      // 32768 chunks of 32
#define NBLOCKS 128
#define NTPB    256

// Per-block partial sums: [block][21 bins]. Fully overwritten every launch -> no init needed.
__device__ float g_part[NBLOCKS][NBITS + 1];

__global__ void __launch_bounds__(NTPB) mil_reduce_kernel(const float* __restrict__ w) {
    const int c    = blockIdx.x * NTPB + threadIdx.x;   // chunk id, 0..32767 (exact cover)
    const int base = c << 5;                            // first element index e of the chunk

    // ---- load 32 elements v[0..31] (e = base+k) ----
    float v[32];
    const float4* __restrict__ w4 = (const float4*)w;
    if (c != NCHUNK - 1) {
#pragma unroll
        for (int g = 0; g < 8; g++) {
            float4 t = w4[(base >> 2) + g];
            v[4*g+0] = t.x; v[4*g+1] = t.y; v[4*g+2] = t.z; v[4*g+3] = t.w;
        }
    } else {
        // last chunk: e = 1048544..1048574 exist; e = 1048575 does not (w has 2^20-1 elems)
#pragma unroll
        for (int g = 0; g < 7; g++) {
            float4 t = w4[(base >> 2) + g];
            v[4*g+0] = t.x; v[4*g+1] = t.y; v[4*g+2] = t.z; v[4*g+3] = t.w;
        }
        v[28] = w[base + 28];
        v[29] = w[base + 29];
        v[30] = w[base + 30];
        v[31] = 0.0f;
    }

    // u[j] = w value whose subset index i has low-5-bits == j (i = base+1+k -> j = k+1)
    // u[0] = 0 (the boundary element v[31] has i = base+32, handled separately)
    float u[32];
    u[0] = 0.0f;
#pragma unroll
    for (int j = 1; j < 32; j++) u[j] = v[j - 1];
    const float v31 = v[31];

    // ---- binary partial-sum tree over u ----
    float T1[16], T2[8], T3[4], T4[2];
#pragma unroll
    for (int k = 0; k < 16; k++) T1[k] = u[2*k] + u[2*k+1];
#pragma unroll
    for (int k = 0; k < 8;  k++) T2[k] = T1[2*k] + T1[2*k+1];
#pragma unroll
    for (int k = 0; k < 4;  k++) T3[k] = T2[2*k] + T2[2*k+1];
#pragma unroll
    for (int k = 0; k < 2;  k++) T4[k] = T3[2*k] + T3[2*k+1];
    const float S = T4[0] + T4[1];      // sum of first 31 elements (i in [base+1, base+31])

    // low-bit sums: B_b = sum over j with bit b of j set
    float B0 = 0.0f, B1 = 0.0f, B2 = 0.0f, B3 = 0.0f;
#pragma unroll
    for (int j = 1; j < 32; j += 2) B0 += u[j];
#pragma unroll
    for (int k = 1; k < 16; k += 2) B1 += T1[k];
#pragma unroll
    for (int k = 1; k < 8;  k += 2) B2 += T2[k];
    B3 = T3[1] + T3[3];
    const float B4 = T4[1];

    // ---- per-chunk contribution vector p[0..20] ----
    float p[NBITS + 1];
    p[0] = B0; p[1] = B1; p[2] = B2; p[3] = B3; p[4] = B4;
    p[NBITS] = S + v31;                 // total-sum bin

    // high bits: bit b (b>=5) of i equals bit (b-5) of c for the 31 in-chunk elements,
    // and bit (b-5) of (c+1) for the boundary element v31 (i = base+32, low bits 0).
    const unsigned cc = (unsigned)c;
    const unsigned c1 = (unsigned)c + 1u;   // c=32767 -> v31=0, so overflow pattern harmless
    const unsigned sb = __float_as_uint(S);
    const unsigned vb = __float_as_uint(v31);
#pragma unroll
    for (int b = 5; b < NBITS; b++) {
        const int sh = 31 - (b - 5);
        unsigned m1 = (unsigned)(((int)(cc << sh)) >> 31);
        unsigned m2 = (unsigned)(((int)(c1 << sh)) >> 31);
        p[b] = __uint_as_float(sb & m1) + __uint_as_float(vb & m2);
    }

    // ---- block reduction of the 21-vector ----
    __shared__ float red[NTPB][NBITS + 2];   // +1 pad to avoid systematic conflicts
    const int tid = threadIdx.x;
#pragma unroll
    for (int b = 0; b <= NBITS; b++) red[tid][b] = p[b];
    __syncthreads();

#pragma unroll
    for (int s = NTPB / 2; s >= 1; s >>= 1) {
        if (tid < s) {
#pragma unroll
            for (int b = 0; b <= NBITS; b++) red[tid][b] += red[tid + s][b];
        }
        __syncthreads();
    }

    if (tid <= NBITS) g_part[blockIdx.x][tid] = red[0][tid];
}

// Combine per-block partials with the O(20) log-prob epilogue.
// All logs in fp32 (MUFU-based logf), parallelized across threads; only the
// final 21-term dot product is done in double (cheap).
__global__ void mil_finalize_kernel(const float* __restrict__ yprob,
                                    const int*   __restrict__ Yp,
                                    int has_Y,
                                    float* __restrict__ out) {
    __shared__ float s[NBITS + 1];
    __shared__ float lp[NBITS], l1[NBITS];
    const int t = threadIdx.x;

    // Parallel gather of per-block partials (21 threads x 128 loads, unrolled)
    if (t <= NBITS) {
        float a0 = 0.0f, a1 = 0.0f, a2 = 0.0f, a3 = 0.0f;
#pragma unroll
        for (int i = 0; i < NBLOCKS; i += 4) {
            a0 += g_part[i + 0][t];
            a1 += g_part[i + 1][t];
            a2 += g_part[i + 2][t];
            a3 += g_part[i + 3][t];
        }
        s[t] = (a0 + a1) + (a2 + a3);
    }

    // Parallel fp32 logs (matches reference: jnp.log in float32)
    if (t < NBITS) {
        float pp = yprob[t];
        lp[t] = logf(pp);
        l1[t] = logf(1.0f - pp);
    }
    __syncthreads();

    if (t == 0) {
        int y_nonzero = 1;
        if (has_Y) y_nonzero = (Yp[0] != 0);

        double basee = 0.0;
#pragma unroll
        for (int j = 0; j < NBITS; j++) basee += (double)l1[j];

        if (y_nonzero) {
            double res = basee * (double)s[NBITS];
#pragma unroll
            for (int b = 0; b < NBITS; b++) {
                int j = NBITS - 1 - b;      // column j <-> bit (NBITS-1-j) of subset index
                res += ((double)lp[j] - (double)l1[j]) * (double)s[b];
            }
            out[0] = (float)res;
        } else {
            out[0] = (float)((double)NSUB * basee);
        }
    }
}

extern "C" void kernel_launch(void* const* d_in, const int* in_sizes, int n_in,
                              void* d_out, int out_size) {
    const float* yprob = (const float*)d_in[0];
    const float* w     = (const float*)d_in[1];
    const int*   Yp    = (n_in >= 3) ? (const int*)d_in[2] : nullptr;
    float*       out   = (float*)d_out;
    (void)in_sizes; (void)out_size;

    mil_reduce_kernel<<<NBLOCKS, NTPB>>>(w);
    mil_finalize_kernel<<<1, 32>>>(yprob, Yp, Yp != nullptr ? 1 : 0, out);
}